// round 16
// baseline (speedup 1.0000x reference)
#include <cuda_runtime.h>
#include <cuda_bf16.h>
#include <cstddef>

#define DDIM 512
#define ROWS 3072

__device__ float  g_ao[ROWS * DDIM];     // unnormalized O_j' from k2
__device__ float2 g_MS[ROWS * 8];        // per (gq,h): (mj, sumj) from k2

// bf16 split buffers
__device__ __align__(16) __nv_bfloat16 g_Ahi[ROWS * DDIM];   // x, then ao (k13)
__device__ __align__(16) __nv_bfloat16 g_Alo[ROWS * DDIM];
__device__ __align__(16) __nv_bfloat16 g_Bhi[DDIM * DDIM];   // Wq
__device__ __align__(16) __nv_bfloat16 g_Blo[DDIM * DDIM];
__device__ __align__(16) __nv_bfloat16 g_B2hi[DDIM * DDIM];  // Wo
__device__ __align__(16) __nv_bfloat16 g_B2lo[DDIM * DDIM];
__device__ __align__(16) __nv_bfloat16 g_qhi[ROWS * DDIM];   // split of q
__device__ __align__(16) __nv_bfloat16 g_qlo[ROWS * DDIM];

__device__ __forceinline__ void ldm4(unsigned* r, unsigned addr) {
    asm volatile("ldmatrix.sync.aligned.m8n8.x4.shared.b16 {%0,%1,%2,%3}, [%4];"
        : "=r"(r[0]), "=r"(r[1]), "=r"(r[2]), "=r"(r[3]) : "r"(addr));
}
__device__ __forceinline__ void ldm2t(unsigned* r, unsigned addr) {
    asm volatile("ldmatrix.sync.aligned.m8n8.x2.trans.shared.b16 {%0,%1}, [%2];"
        : "=r"(r[0]), "=r"(r[1]) : "r"(addr));
}
__device__ __forceinline__ void mma_bf16(float* c, const unsigned* a, const unsigned* b) {
    asm volatile(
        "mma.sync.aligned.m16n8k16.row.col.f32.bf16.bf16.f32 "
        "{%0,%1,%2,%3}, {%4,%5,%6,%7}, {%8,%9}, {%0,%1,%2,%3};"
        : "+f"(c[0]), "+f"(c[1]), "+f"(c[2]), "+f"(c[3])
        : "r"(a[0]), "r"(a[1]), "r"(a[2]), "r"(a[3]), "r"(b[0]), "r"(b[1]));
}
__device__ __forceinline__ void cpa16(unsigned saddr, const void* gptr) {
    asm volatile("cp.async.cg.shared.global [%0], [%1], 16;" :: "r"(saddr), "l"(gptr));
}
__device__ __forceinline__ unsigned scvt(const void* p) {
    return (unsigned)__cvta_generic_to_shared(p);
}
__device__ __forceinline__ void split8(const float* s, __nv_bfloat16* hi, __nv_bfloat16* lo) {
    __nv_bfloat162 H[4], L[4];
    #pragma unroll
    for (int u = 0; u < 4; u++) {
        __nv_bfloat16 h0 = __float2bfloat16_rn(s[2*u]);
        __nv_bfloat16 h1 = __float2bfloat16_rn(s[2*u+1]);
        H[u] = __nv_bfloat162(h0, h1);
        L[u] = __nv_bfloat162(__float2bfloat16_rn(s[2*u]   - __bfloat162float(h0)),
                              __float2bfloat16_rn(s[2*u+1] - __bfloat162float(h1)));
    }
    *(uint4*)hi = *(const uint4*)H;
    *(uint4*)lo = *(const uint4*)L;
}

#define NX4 (ROWS * DDIM / 4)
#define NW4 (DDIM * DDIM / 4)

// ---------------------------------------------------------------------------
// Fused split: x -> Ahi/Alo, Wq -> Bhi/Blo, Wo -> B2hi/B2lo.
// ---------------------------------------------------------------------------
__global__ __launch_bounds__(256) void split_all(
    const float* __restrict__ x, const float* __restrict__ Wq,
    const float* __restrict__ Wo)
{
    int idx = blockIdx.x * 256 + threadIdx.x;
    const float* src; __nv_bfloat16 *hi, *lo; int b;
    if (idx < NX4)            { src = x;  hi = g_Ahi;  lo = g_Alo;  b = idx; }
    else if (idx < NX4 + NW4) { src = Wq; hi = g_Bhi;  lo = g_Blo;  b = idx - NX4; }
    else                      { src = Wo; hi = g_B2hi; lo = g_B2lo; b = idx - NX4 - NW4; }
    float4 v = ((const float4*)src)[b];
    __nv_bfloat16 h0 = __float2bfloat16_rn(v.x);
    __nv_bfloat16 h1 = __float2bfloat16_rn(v.y);
    __nv_bfloat16 h2 = __float2bfloat16_rn(v.z);
    __nv_bfloat16 h3 = __float2bfloat16_rn(v.w);
    ((__nv_bfloat162*)hi)[b*2]   = __nv_bfloat162(h0, h1);
    ((__nv_bfloat162*)hi)[b*2+1] = __nv_bfloat162(h2, h3);
    ((__nv_bfloat162*)lo)[b*2]   = __nv_bfloat162(
        __float2bfloat16_rn(v.x - __bfloat162float(h0)),
        __float2bfloat16_rn(v.y - __bfloat162float(h1)));
    ((__nv_bfloat162*)lo)[b*2+1] = __nv_bfloat162(
        __float2bfloat16_rn(v.z - __bfloat162float(h2)),
        __float2bfloat16_rn(v.w - __bfloat162float(h3)));
}

// ---------------------------------------------------------------------------
// GEMM (verified r9/r12 config: BM=BN=64, BK=32, 128 thr, static smem).
// ---------------------------------------------------------------------------
#define PITCH 40

__global__ __launch_bounds__(128) void gemm_bf16(
    const __nv_bfloat16* __restrict__ Ahi, const __nv_bfloat16* __restrict__ Alo,
    const __nv_bfloat16* __restrict__ Bhi, const __nv_bfloat16* __restrict__ Blo,
    const float* __restrict__ bias, float* __restrict__ C,
    __nv_bfloat16* __restrict__ Chi, __nv_bfloat16* __restrict__ Clo,
    int M, int N, int K)
{
    __shared__ __nv_bfloat16 sA[2][2][64][PITCH];
    __shared__ __nv_bfloat16 sB[2][2][64][PITCH];

    const int bm = blockIdx.y * 64;
    const int bn = blockIdx.x * 64;
    const int tid  = threadIdx.x;
    const int warp = tid >> 5;
    const int lane = tid & 31;
    const int wm = warp & 1;
    const int wn = warp >> 1;
    const int NS = K / 32;

    const __nv_bfloat16* gsrc[4] = { Ahi, Alo, Bhi, Blo };

    auto issue = [&](int s) {
        const int k0 = s * 32;
        const int buf = s & 1;
        #pragma unroll
        for (int it = 0; it < 8; it++) {
            int idx = tid + 128 * it;
            int sel = idx >> 8;
            int c   = idx & 255;
            int row = c >> 2, ch = c & 3;
            const __nv_bfloat16* gp = gsrc[sel] +
                (size_t)((sel < 2 ? bm : bn) + row) * K + k0 + ch * 8;
            __nv_bfloat16* sp = (sel < 2)
                ? &sA[buf][sel][row][ch * 8]
                : &sB[buf][sel - 2][row][ch * 8];
            cpa16(scvt(sp), gp);
        }
        asm volatile("cp.async.commit_group;");
    };

    float acc[2][4][4];
    #pragma unroll
    for (int mt = 0; mt < 2; mt++)
        #pragma unroll
        for (int nt = 0; nt < 4; nt++)
            #pragma unroll
            for (int u = 0; u < 4; u++) acc[mt][nt][u] = 0.f;

    issue(0);

    for (int s = 0; s < NS; s++) {
        if (s + 1 < NS) { issue(s + 1); asm volatile("cp.async.wait_group 1;"); }
        else            { asm volatile("cp.async.wait_group 0;"); }
        __syncthreads();
        const int buf = s & 1;

        #pragma unroll
        for (int kk = 0; kk < 2; kk++) {
            unsigned ah[2][4], al[2][4];
            #pragma unroll
            for (int mt = 0; mt < 2; mt++) {
                int row = wm * 32 + mt * 16 + (lane & 15);
                int col = kk * 16 + (lane >> 4) * 8;
                ldm4(ah[mt], scvt(&sA[buf][0][row][col]));
                ldm4(al[mt], scvt(&sA[buf][1][row][col]));
            }
            unsigned bh[4][2], bl[4][2];
            #pragma unroll
            for (int nt = 0; nt < 4; nt++) {
                int n = wn * 32 + nt * 8 + (lane >> 2);
                int w0 = kk * 16 + (lane & 3) * 2;
                bh[nt][0] = *(const unsigned*)&sB[buf][0][n][w0];
                bh[nt][1] = *(const unsigned*)&sB[buf][0][n][w0 + 8];
                bl[nt][0] = *(const unsigned*)&sB[buf][1][n][w0];
                bl[nt][1] = *(const unsigned*)&sB[buf][1][n][w0 + 8];
            }
            #pragma unroll
            for (int mt = 0; mt < 2; mt++)
                #pragma unroll
                for (int nt = 0; nt < 4; nt++) {
                    mma_bf16(acc[mt][nt], ah[mt], bl[nt]);
                    mma_bf16(acc[mt][nt], al[mt], bh[nt]);
                    mma_bf16(acc[mt][nt], ah[mt], bh[nt]);
                }
        }
        __syncthreads();
    }

    const int r4 = lane >> 2;
    const int kq = lane & 3;
    #pragma unroll
    for (int nt = 0; nt < 4; nt++) {
        int col = bn + wn * 32 + nt * 8 + 2 * kq;
        float2 bb = make_float2(0.f, 0.f);
        if (bias) bb = *(const float2*)(bias + col);
        #pragma unroll
        for (int mt = 0; mt < 2; mt++) {
            int row0 = bm + wm * 32 + mt * 16 + r4;
            float2 v0 = make_float2(acc[mt][nt][0] + bb.x, acc[mt][nt][1] + bb.y);
            float2 v1 = make_float2(acc[mt][nt][2] + bb.x, acc[mt][nt][3] + bb.y);
            if (C) {
                *(float2*)(C + (size_t)row0 * N + col) = v0;
                *(float2*)(C + (size_t)(row0 + 8) * N + col) = v1;
            }
            if (Chi) {
                __nv_bfloat16 h0 = __float2bfloat16_rn(v0.x);
                __nv_bfloat16 h1 = __float2bfloat16_rn(v0.y);
                __nv_bfloat16 h2 = __float2bfloat16_rn(v1.x);
                __nv_bfloat16 h3 = __float2bfloat16_rn(v1.y);
                *(__nv_bfloat162*)(Chi + (size_t)row0 * N + col) = __nv_bfloat162(h0, h1);
                *(__nv_bfloat162*)(Chi + (size_t)(row0 + 8) * N + col) = __nv_bfloat162(h2, h3);
                *(__nv_bfloat162*)(Clo + (size_t)row0 * N + col) = __nv_bfloat162(
                    __float2bfloat16_rn(v0.x - __bfloat162float(h0)),
                    __float2bfloat16_rn(v0.y - __bfloat162float(h1)));
                *(__nv_bfloat162*)(Clo + (size_t)(row0 + 8) * N + col) = __nv_bfloat162(
                    __float2bfloat16_rn(v1.x - __bfloat162float(h2)),
                    __float2bfloat16_rn(v1.y - __bfloat162float(h3)));
            }
        }
    }
}

// ---------------------------------------------------------------------------
// Key index mapping (verified rounds 1-15).
// ---------------------------------------------------------------------------
__device__ __forceinline__ int key_gpos(int p, int f, int i, int j)
{
    const int g = f >> 5;
    const int r = f & 31;
    int pos, sp;
    if (p == 0) {
        sp = (f < 64) ? 1 : 2;
        pos = (g == 0) ? r * 32 + i
            : (g == 1) ? 480 + r
            : (g == 2) ? r * 32 + 15
            :            j * 32 + r;
    } else if (p == 1) {
        sp = (f < 64) ? 0 : 2;
        pos = (g == 0) ? r * 32 + i
            : (g == 1) ? 480 + r
            : (g == 2) ? r * 32 + (31 - j)
            :            480 + r;
    } else {
        sp = (f < 64) ? 0 : 2;
        pos = (g == 0) ? r * 32 + 15
            : (g == 1) ? j * 32 + r
            : (g == 2) ? r * 32 + 15
            :            (31 - i) * 32 + r;
    }
    return sp * 1024 + pos;
}

__device__ __forceinline__ int k1_f(int p, int s)
{
    int g = s >> 5;
    if (g >= 3 - p) g++;
    return g * 32 + (s & 31);
}

// ---------------------------------------------------------------------------
// K2 (verified r15, 256 threads): j-dep scores + local softmax (mj,sumj) +
// unnormalized O_j' -> g_ao. CTA = (j, h, p).
// ---------------------------------------------------------------------------
__global__ __launch_bounds__(256) void k2_mid()
{
    const int j = blockIdx.x, h = blockIdx.y, p = blockIdx.z;
    const int tid = threadIdx.x;
    const int warp = tid >> 5, lane = tid & 31;
    const int wm = warp & 1, wn = warp >> 1;     // wn in 0..3
    const int qbase = p * 1024 + j * 32;

    __shared__ int spos[32];
    __shared__ __align__(16) __nv_bfloat16 Qh[32][72], Ql[32][72];
    __shared__ __align__(16) __nv_bfloat16 Kh[32][72], Kl[32][72];
    __shared__ float Sj[32][36];
    __shared__ __align__(16) __nv_bfloat16 Pjh[32][40], Pjl[32][40];

    if (tid < 32) spos[tid] = key_gpos(p, (3 - p) * 32 + tid, 0, j);
    __syncthreads();

    {
        int row = tid >> 3, ch = (tid & 7) * 8;
        size_t qo = (size_t)(qbase + row) * DDIM + h * 64 + ch;
        cpa16(scvt(&Qh[row][ch]), g_qhi + qo);
        cpa16(scvt(&Ql[row][ch]), g_qlo + qo);
        size_t ko = (size_t)spos[row] * DDIM + h * 64 + ch;
        cpa16(scvt(&Kh[row][ch]), g_qhi + ko);
        cpa16(scvt(&Kl[row][ch]), g_qlo + ko);
    }
    asm volatile("cp.async.commit_group;");
    asm volatile("cp.async.wait_group 0;");
    __syncthreads();

    const int r4 = lane >> 2, kq = lane & 3;

    // S_j(32q x 32f) = Q @ Kj^T : warp = (wm m-tile) x (wn 8 f-cols)
    {
        float sacc[4] = {0.f, 0.f, 0.f, 0.f};
        #pragma unroll
        for (int kk = 0; kk < 4; kk++) {
            unsigned ah[4], al[4];
            const int arow = wm * 16 + (lane & 15);
            const int acol = kk * 16 + (lane >> 4) * 8;
            ldm4(ah, scvt(&Qh[arow][acol]));
            ldm4(al, scvt(&Ql[arow][acol]));
            unsigned bh[2], bl[2];
            int n = wn * 8 + (lane >> 2);
            int c0 = kk * 16 + (lane & 3) * 2;
            bh[0] = *(const unsigned*)&Kh[n][c0];
            bh[1] = *(const unsigned*)&Kh[n][c0 + 8];
            bl[0] = *(const unsigned*)&Kl[n][c0];
            bl[1] = *(const unsigned*)&Kl[n][c0 + 8];
            mma_bf16(sacc, ah, bl);
            mma_bf16(sacc, al, bh);
            mma_bf16(sacc, ah, bh);
        }
        int q0 = wm * 16 + r4;
        int f = wn * 8 + 2 * kq;
        Sj[q0][f]       = sacc[0] * 0.125f;
        Sj[q0][f + 1]   = sacc[1] * 0.125f;
        Sj[q0 + 8][f]     = sacc[2] * 0.125f;
        Sj[q0 + 8][f + 1] = sacc[3] * 0.125f;
    }
    __syncthreads();

    // local softmax + Pj split on threads 0..127
    if (tid < 128) {
        const int qs = tid >> 2, l4 = tid & 3;
        float vals[8];
        float mj = -1e30f;
        #pragma unroll
        for (int u = 0; u < 8; u++) {
            vals[u] = Sj[qs][l4 + 4 * u];
            mj = fmaxf(mj, vals[u]);
        }
        mj = fmaxf(mj, __shfl_xor_sync(0xffffffffu, mj, 2));
        mj = fmaxf(mj, __shfl_xor_sync(0xffffffffu, mj, 1));
        float sumj = 0.f;
        #pragma unroll
        for (int u = 0; u < 8; u++) { vals[u] = __expf(vals[u] - mj); sumj += vals[u]; }
        sumj += __shfl_xor_sync(0xffffffffu, sumj, 2);
        sumj += __shfl_xor_sync(0xffffffffu, sumj, 1);
        if (l4 == 0)
            g_MS[(unsigned)(qbase + qs) * 8 + h] = make_float2(mj, sumj);
        #pragma unroll
        for (int u = 0; u < 8; u++)
            Sj[qs][l4 + 4 * u] = vals[u];
        __syncwarp();
        split8(&Sj[qs][l4 * 8], &Pjh[qs][l4 * 8], &Pjl[qs][l4 * 8]);
    }
    __syncthreads();

    // O_j'(32q x 64d) = P_j'(32x32) @ K_j(32x64): warp = wm x (wn 16 d-cols)
    {
        float oacc[2][4];
        #pragma unroll
        for (int nt = 0; nt < 2; nt++)
            #pragma unroll
            for (int u = 0; u < 4; u++) oacc[nt][u] = 0.f;

        #pragma unroll
        for (int ks = 0; ks < 2; ks++) {
            const int k0 = ks * 16;
            unsigned ah[4], al[4];
            const int arow = wm * 16 + (lane & 15);
            const int acol = k0 + (lane >> 4) * 8;
            ldm4(ah, scvt(&Pjh[arow][acol]));
            ldm4(al, scvt(&Pjl[arow][acol]));
            unsigned bh[2][2], bl[2][2];
            const int brow = k0 + (lane & 7) + 8 * ((lane >> 3) & 1);
            #pragma unroll
            for (int nt = 0; nt < 2; nt++) {
                int bcol = wn * 16 + nt * 8;
                ldm2t(bh[nt], scvt(&Kh[brow][bcol]));
                ldm2t(bl[nt], scvt(&Kl[brow][bcol]));
            }
            #pragma unroll
            for (int nt = 0; nt < 2; nt++) {
                mma_bf16(oacc[nt], ah, bl[nt]);
                mma_bf16(oacc[nt], al, bh[nt]);
                mma_bf16(oacc[nt], ah, bh[nt]);
            }
        }
        #pragma unroll
        for (int nt = 0; nt < 2; nt++) {
            int d = wn * 16 + nt * 8 + 2 * kq;
            #pragma unroll
            for (int half = 0; half < 2; half++) {
                int q0 = wm * 16 + r4 + half * 8;
                *(float2*)(g_ao + (size_t)(qbase + q0) * DDIM + h * 64 + d) =
                    make_float2(oacc[nt][half*2], oacc[nt][half*2+1]);
            }
        }
    }
}

// ---------------------------------------------------------------------------
// K13 (fused k1+k3), 256 threads. Smem union: P overlays Q (dead after
// score phase; two barriers separate last Q read from first P write).
// 41.8 KB -> 5 CTAs/SM. Epilogue g_ao/coef loads hoisted above output MMA.
// ---------------------------------------------------------------------------
struct K13Smem {
    int spos[96];
    float2 pstat[4][32];    // [wn][row] partial (m, s)
    float2 minv[32];        // per row: (m, 1/total)
    float  coef[32];        // per row: e^(mj-m)/total
    union {
        struct {
            __align__(16) __nv_bfloat16 Qh[32][72];
            __align__(16) __nv_bfloat16 Ql[32][72];
        } q;
        struct {
            __align__(16) __nv_bfloat16 Ph[32][104];
            __align__(16) __nv_bfloat16 Pl[32][104];
        } pp;
    } u;
    __align__(16) __nv_bfloat16 Kh[96][72];
    __align__(16) __nv_bfloat16 Kl[96][72];
};

__global__ __launch_bounds__(256) void k13_fused()
{
    const int i = blockIdx.x, h = blockIdx.y, p = blockIdx.z;
    const int tid = threadIdx.x;
    const int warp = tid >> 5, lane = tid & 31;
    const int wm = warp & 1, wn = warp >> 1;   // wn in 0..3

    extern __shared__ char raw13[];
    K13Smem* sm = (K13Smem*)raw13;

    if (tid < 96) sm->spos[tid] = key_gpos(p, k1_f(p, tid), i, 0);
    __syncthreads();

    // group A: Q + K rows 0..47
    {
        int row = tid >> 3, ch = (tid & 7) * 8;
        size_t off = (size_t)(p * 1024 + row * 32 + i) * DDIM + h * 64 + ch;
        cpa16(scvt(&sm->u.q.Qh[row][ch]), g_qhi + off);
        cpa16(scvt(&sm->u.q.Ql[row][ch]), g_qlo + off);
    }
    #pragma unroll
    for (int it = 0; it < 2; it++) {
        int idx = tid + 256 * it;                  // need 0..383 (48 rows x 8)
        if (idx < 384) {
            int row = idx >> 3, ch = (idx & 7) * 8;
            size_t off = (size_t)sm->spos[row] * DDIM + h * 64 + ch;
            cpa16(scvt(&sm->Kh[row][ch]), g_qhi + off);
            cpa16(scvt(&sm->Kl[row][ch]), g_qlo + off);
        }
    }
    asm volatile("cp.async.commit_group;");
    // group B: K rows 48..95
    #pragma unroll
    for (int it = 0; it < 2; it++) {
        int idx = tid + 256 * it;
        if (idx < 384) {
            int row = 48 + (idx >> 3), ch = (idx & 7) * 8;
            size_t off = (size_t)sm->spos[row] * DDIM + h * 64 + ch;
            cpa16(scvt(&sm->Kh[row][ch]), g_qhi + off);
            cpa16(scvt(&sm->Kl[row][ch]), g_qlo + off);
        }
    }
    asm volatile("cp.async.commit_group;");

    asm volatile("cp.async.wait_group 1;");
    __syncthreads();                                // Q + K[0..48) visible

    const int r4 = lane >> 2, kq = lane & 3;

    float acc[3][4];
    #pragma unroll
    for (int nt = 0; nt < 3; nt++)
        #pragma unroll
        for (int u = 0; u < 4; u++) acc[nt][u] = 0.f;

    auto score_phase = [&]() {
        #pragma unroll
        for (int kk = 0; kk < 4; kk++) {
            unsigned ah[4], al[4];
            const int arow = wm * 16 + (lane & 15);
            const int acol = kk * 16 + (lane >> 4) * 8;
            ldm4(ah, scvt(&sm->u.q.Qh[arow][acol]));
            ldm4(al, scvt(&sm->u.q.Ql[arow][acol]));
            unsigned bh[3][2], bl[3][2];
            #pragma unroll
            for (int nt = 0; nt < 3; nt++) {
                int n = wn * 24 + nt * 8 + (lane >> 2);
                int c0 = kk * 16 + (lane & 3) * 2;
                bh[nt][0] = *(const unsigned*)&sm->Kh[n][c0];
                bh[nt][1] = *(const unsigned*)&sm->Kh[n][c0 + 8];
                bl[nt][0] = *(const unsigned*)&sm->Kl[n][c0];
                bl[nt][1] = *(const unsigned*)&sm->Kl[n][c0 + 8];
            }
            #pragma unroll
            for (int nt = 0; nt < 3; nt++) {
                mma_bf16(acc[nt], ah, bl[nt]);
                mma_bf16(acc[nt], al, bh[nt]);
                mma_bf16(acc[nt], ah, bh[nt]);
            }
        }
        #pragma unroll
        for (int nt = 0; nt < 3; nt++)
            #pragma unroll
            for (int u = 0; u < 4; u++) acc[nt][u] *= 0.125f;

        #pragma unroll
        for (int half = 0; half < 2; half++) {
            float m = -1e30f;
            #pragma unroll
            for (int nt = 0; nt < 3; nt++) {
                m = fmaxf(m, acc[nt][half*2]);
                m = fmaxf(m, acc[nt][half*2+1]);
            }
            m = fmaxf(m, __shfl_xor_sync(0xffffffffu, m, 1));
            m = fmaxf(m, __shfl_xor_sync(0xffffffffu, m, 2));
            float s = 0.f;
            #pragma unroll
            for (int nt = 0; nt < 3; nt++) {
                s += __expf(acc[nt][half*2]   - m);
                s += __expf(acc[nt][half*2+1] - m);
            }
            s += __shfl_xor_sync(0xffffffffu, s, 1);
            s += __shfl_xor_sync(0xffffffffu, s, 2);
            if (kq == 0)
                sm->pstat[wn][wm*16 + half*8 + r4] = make_float2(m, s);
        }
    };

    if (wn < 2) score_phase();          // slots 0..47 only
    asm volatile("cp.async.wait_group 0;");
    __syncthreads();                     // K[48..96) visible
    if (wn >= 2) score_phase();          // slots 48..95
    __syncthreads();                     // (also: last Q read is above)

    // ---- combine with (mj, sumj): one thread per row ----
    if (tid < 32) {
        int row = tid;
        float m = sm->pstat[0][row].x;
        m = fmaxf(m, sm->pstat[1][row].x);
        m = fmaxf(m, sm->pstat[2][row].x);
        m = fmaxf(m, sm->pstat[3][row].x);
        float2 msj = g_MS[(unsigned)(p*1024 + row*32 + i) * 8 + h];
        m = fmaxf(m, msj.x);
        float tot = msj.y * __expf(msj.x - m);
        #pragma unroll
        for (int w = 0; w < 4; w++)
            tot += sm->pstat[w][row].y * __expf(sm->pstat[w][row].x - m);
        float inv = 1.0f / tot;
        sm->minv[row] = make_float2(m, inv);
        sm->coef[row] = __expf(msj.x - m) * inv;
    }
    __syncthreads();

    // ---- normalize in registers, write bf16 P split to smem (over Q) ----
    {
        const int q0 = wm * 16 + r4;
        const int q1 = q0 + 8;
        float2 mi0 = sm->minv[q0];
        float2 mi1 = sm->minv[q1];
        #pragma unroll
        for (int nt = 0; nt < 3; nt++) {
            int slot = wn * 24 + nt * 8 + 2 * kq;
            float p0 = __expf(acc[nt][0] - mi0.x) * mi0.y;
            float p1 = __expf(acc[nt][1] - mi0.x) * mi0.y;
            float p2 = __expf(acc[nt][2] - mi1.x) * mi1.y;
            float p3 = __expf(acc[nt][3] - mi1.x) * mi1.y;
            __nv_bfloat16 h0 = __float2bfloat16_rn(p0);
            __nv_bfloat16 h1 = __float2bfloat16_rn(p1);
            __nv_bfloat16 h2 = __float2bfloat16_rn(p2);
            __nv_bfloat16 h3 = __float2bfloat16_rn(p3);
            *(__nv_bfloat162*)&sm->u.pp.Ph[q0][slot] = __nv_bfloat162(h0, h1);
            *(__nv_bfloat162*)&sm->u.pp.Ph[q1][slot] = __nv_bfloat162(h2, h3);
            *(__nv_bfloat162*)&sm->u.pp.Pl[q0][slot] = __nv_bfloat162(
                __float2bfloat16_rn(p0 - __bfloat162float(h0)),
                __float2bfloat16_rn(p1 - __bfloat162float(h1)));
            *(__nv_bfloat162*)&sm->u.pp.Pl[q1][slot] = __nv_bfloat162(
                __float2bfloat16_rn(p2 - __bfloat162float(h2)),
                __float2bfloat16_rn(p3 - __bfloat162float(h3)));
        }
    }
    __syncthreads();

    // ---- hoist epilogue inputs (coef + old O_j') above the output MMA ----
    float  cf[2];
    float2 oldv[2][2];
    size_t offs[2][2];
    #pragma unroll
    for (int half = 0; half < 2; half++) {
        int q0 = wm * 16 + r4 + half * 8;
        cf[half] = sm->coef[q0];
        #pragma unroll
        for (int nt = 0; nt < 2; nt++) {
            int d = wn * 16 + nt * 8 + 2 * kq;
            offs[nt][half] = (size_t)(p*1024 + q0*32 + i) * DDIM + h*64 + d;
            oldv[nt][half] = *(const float2*)(g_ao + offs[nt][half]);
        }
    }

    // ---- output MMA: warp = m-tile wm x 16 d-cols (wn*16..wn*16+15) ----
    float oacc[2][4];
    #pragma unroll
    for (int nt = 0; nt < 2; nt++)
        #pragma unroll
        for (int u = 0; u < 4; u++) oacc[nt][u] = 0.f;

    #pragma unroll
    for (int ks = 0; ks < 6; ks++) {
        const int k0 = ks * 16;
        unsigned ah[4], al[4];
        const int arow = wm * 16 + (lane & 15);
        const int acol = k0 + (lane >> 4) * 8;
        ldm4(ah, scvt(&sm->u.pp.Ph[arow][acol]));
        ldm4(al, scvt(&sm->u.pp.Pl[arow][acol]));
        unsigned bh[2][2], bl[2][2];
        const int brow = k0 + (lane & 7) + 8 * ((lane >> 3) & 1);
        #pragma unroll
        for (int nt = 0; nt < 2; nt++) {
            int bcol = wn * 16 + nt * 8;
            ldm2t(bh[nt], scvt(&sm->Kh[brow][bcol]));
            ldm2t(bl[nt], scvt(&sm->Kl[brow][bcol]));
        }
        #pragma unroll
        for (int nt = 0; nt < 2; nt++) {
            mma_bf16(oacc[nt], ah, bl[nt]);
            mma_bf16(oacc[nt], al, bh[nt]);
            mma_bf16(oacc[nt], ah, bh[nt]);
        }
    }

    // ---- epilogue: O = O96 + coef * O_j'; write ao bf16 split ----
    #pragma unroll
    for (int nt = 0; nt < 2; nt++) {
        #pragma unroll
        for (int half = 0; half < 2; half++) {
            float c = cf[half];
            float v0 = oacc[nt][half * 2]     + c * oldv[nt][half].x;
            float v1 = oacc[nt][half * 2 + 1] + c * oldv[nt][half].y;
            __nv_bfloat16 h0 = __float2bfloat16_rn(v0);
            __nv_bfloat16 h1 = __float2bfloat16_rn(v1);
            *(__nv_bfloat162*)(g_Ahi + offs[nt][half]) = __nv_bfloat162(h0, h1);
            *(__nv_bfloat162*)(g_Alo + offs[nt][half]) = __nv_bfloat162(
                __float2bfloat16_rn(v0 - __bfloat162float(h0)),
                __float2bfloat16_rn(v1 - __bfloat162float(h1)));
        }
    }
}

// ---------------------------------------------------------------------------
extern "C" void kernel_launch(void* const* d_in, const int* in_sizes, int n_in,
                              void* d_out, int out_size)
{
    const float* x  = (const float*)d_in[0];
    const float* Wq = (const float*)d_in[1];
    const float* Wo = (const float*)d_in[2];
    const float* bo = (const float*)d_in[3];
    float* out = (float*)d_out;

    __nv_bfloat16 *ahi, *alo, *bhi, *blo, *b2hi, *b2lo, *qhi, *qlo;
    cudaGetSymbolAddress((void**)&ahi,  g_Ahi);
    cudaGetSymbolAddress((void**)&alo,  g_Alo);
    cudaGetSymbolAddress((void**)&bhi,  g_Bhi);
    cudaGetSymbolAddress((void**)&blo,  g_Blo);
    cudaGetSymbolAddress((void**)&b2hi, g_B2hi);
    cudaGetSymbolAddress((void**)&b2lo, g_B2lo);
    cudaGetSymbolAddress((void**)&qhi,  g_qhi);
    cudaGetSymbolAddress((void**)&qlo,  g_qlo);

    cudaFuncSetAttribute(k13_fused, cudaFuncAttributeMaxDynamicSharedMemorySize,
                         (int)sizeof(K13Smem));

    const dim3 gridG(512 / 64, ROWS / 64);  // (8, 48)
    const dim3 gridA(32, 8, 3);

    split_all<<<(NX4 + 2 * NW4) / 256, 256>>>(x, Wq, Wo);
    gemm_bf16<<<gridG, 128>>>(ahi, alo, bhi, blo, nullptr, nullptr, qhi, qlo,
                              ROWS, 512, 512);
    k2_mid   <<<gridA, 256>>>();
    k13_fused<<<gridA, 256, sizeof(K13Smem)>>>();
    gemm_bf16<<<gridG, 128>>>(ahi, alo, b2hi, b2lo, bo, out, nullptr, nullptr,
                              ROWS, 512, 512);
}

// round 17
// speedup vs baseline: 1.0478x; 1.0478x over previous
#include <cuda_runtime.h>
#include <cuda_bf16.h>
#include <cstddef>

#define DDIM 512
#define ROWS 3072

__device__ float  g_ao[ROWS * DDIM];     // unnormalized O_j' from k2
__device__ float2 g_MS[ROWS * 8];        // per (gq,h): (mj, sumj) from k2

// bf16 split buffers
__device__ __align__(16) __nv_bfloat16 g_Ahi[ROWS * DDIM];   // x, then ao (k13)
__device__ __align__(16) __nv_bfloat16 g_Alo[ROWS * DDIM];
__device__ __align__(16) __nv_bfloat16 g_Bhi[DDIM * DDIM];   // Wq
__device__ __align__(16) __nv_bfloat16 g_Blo[DDIM * DDIM];
__device__ __align__(16) __nv_bfloat16 g_B2hi[DDIM * DDIM];  // Wo
__device__ __align__(16) __nv_bfloat16 g_B2lo[DDIM * DDIM];
__device__ __align__(16) __nv_bfloat16 g_qhi[ROWS * DDIM];   // split of q
__device__ __align__(16) __nv_bfloat16 g_qlo[ROWS * DDIM];

__device__ __forceinline__ void ldm4(unsigned* r, unsigned addr) {
    asm volatile("ldmatrix.sync.aligned.m8n8.x4.shared.b16 {%0,%1,%2,%3}, [%4];"
        : "=r"(r[0]), "=r"(r[1]), "=r"(r[2]), "=r"(r[3]) : "r"(addr));
}
__device__ __forceinline__ void ldm2t(unsigned* r, unsigned addr) {
    asm volatile("ldmatrix.sync.aligned.m8n8.x2.trans.shared.b16 {%0,%1}, [%2];"
        : "=r"(r[0]), "=r"(r[1]) : "r"(addr));
}
__device__ __forceinline__ void mma_bf16(float* c, const unsigned* a, const unsigned* b) {
    asm volatile(
        "mma.sync.aligned.m16n8k16.row.col.f32.bf16.bf16.f32 "
        "{%0,%1,%2,%3}, {%4,%5,%6,%7}, {%8,%9}, {%0,%1,%2,%3};"
        : "+f"(c[0]), "+f"(c[1]), "+f"(c[2]), "+f"(c[3])
        : "r"(a[0]), "r"(a[1]), "r"(a[2]), "r"(a[3]), "r"(b[0]), "r"(b[1]));
}
__device__ __forceinline__ void cpa16(unsigned saddr, const void* gptr) {
    asm volatile("cp.async.cg.shared.global [%0], [%1], 16;" :: "r"(saddr), "l"(gptr));
}
__device__ __forceinline__ unsigned scvt(const void* p) {
    return (unsigned)__cvta_generic_to_shared(p);
}
__device__ __forceinline__ void split8(const float* s, __nv_bfloat16* hi, __nv_bfloat16* lo) {
    __nv_bfloat162 H[4], L[4];
    #pragma unroll
    for (int u = 0; u < 4; u++) {
        __nv_bfloat16 h0 = __float2bfloat16_rn(s[2*u]);
        __nv_bfloat16 h1 = __float2bfloat16_rn(s[2*u+1]);
        H[u] = __nv_bfloat162(h0, h1);
        L[u] = __nv_bfloat162(__float2bfloat16_rn(s[2*u]   - __bfloat162float(h0)),
                              __float2bfloat16_rn(s[2*u+1] - __bfloat162float(h1)));
    }
    *(uint4*)hi = *(const uint4*)H;
    *(uint4*)lo = *(const uint4*)L;
}

#define NX4 (ROWS * DDIM / 4)
#define NW4 (DDIM * DDIM / 4)

// ---------------------------------------------------------------------------
// Fused split: x -> Ahi/Alo, Wq -> Bhi/Blo, Wo -> B2hi/B2lo.
// ---------------------------------------------------------------------------
__global__ __launch_bounds__(256) void split_all(
    const float* __restrict__ x, const float* __restrict__ Wq,
    const float* __restrict__ Wo)
{
    int idx = blockIdx.x * 256 + threadIdx.x;
    const float* src; __nv_bfloat16 *hi, *lo; int b;
    if (idx < NX4)            { src = x;  hi = g_Ahi;  lo = g_Alo;  b = idx; }
    else if (idx < NX4 + NW4) { src = Wq; hi = g_Bhi;  lo = g_Blo;  b = idx - NX4; }
    else                      { src = Wo; hi = g_B2hi; lo = g_B2lo; b = idx - NX4 - NW4; }
    float4 v = ((const float4*)src)[b];
    __nv_bfloat16 h0 = __float2bfloat16_rn(v.x);
    __nv_bfloat16 h1 = __float2bfloat16_rn(v.y);
    __nv_bfloat16 h2 = __float2bfloat16_rn(v.z);
    __nv_bfloat16 h3 = __float2bfloat16_rn(v.w);
    ((__nv_bfloat162*)hi)[b*2]   = __nv_bfloat162(h0, h1);
    ((__nv_bfloat162*)hi)[b*2+1] = __nv_bfloat162(h2, h3);
    ((__nv_bfloat162*)lo)[b*2]   = __nv_bfloat162(
        __float2bfloat16_rn(v.x - __bfloat162float(h0)),
        __float2bfloat16_rn(v.y - __bfloat162float(h1)));
    ((__nv_bfloat162*)lo)[b*2+1] = __nv_bfloat162(
        __float2bfloat16_rn(v.z - __bfloat162float(h2)),
        __float2bfloat16_rn(v.w - __bfloat162float(h3)));
}

// ---------------------------------------------------------------------------
// GEMM (verified r9/r12 config). PDL: waits for predecessor at top.
// ---------------------------------------------------------------------------
#define PITCH 40

__global__ __launch_bounds__(128) void gemm_bf16(
    const __nv_bfloat16* __restrict__ Ahi, const __nv_bfloat16* __restrict__ Alo,
    const __nv_bfloat16* __restrict__ Bhi, const __nv_bfloat16* __restrict__ Blo,
    const float* __restrict__ bias, float* __restrict__ C,
    __nv_bfloat16* __restrict__ Chi, __nv_bfloat16* __restrict__ Clo,
    int M, int N, int K)
{
    cudaGridDependencySynchronize();

    __shared__ __nv_bfloat16 sA[2][2][64][PITCH];
    __shared__ __nv_bfloat16 sB[2][2][64][PITCH];

    const int bm = blockIdx.y * 64;
    const int bn = blockIdx.x * 64;
    const int tid  = threadIdx.x;
    const int warp = tid >> 5;
    const int lane = tid & 31;
    const int wm = warp & 1;
    const int wn = warp >> 1;
    const int NS = K / 32;

    const __nv_bfloat16* gsrc[4] = { Ahi, Alo, Bhi, Blo };

    auto issue = [&](int s) {
        const int k0 = s * 32;
        const int buf = s & 1;
        #pragma unroll
        for (int it = 0; it < 8; it++) {
            int idx = tid + 128 * it;
            int sel = idx >> 8;
            int c   = idx & 255;
            int row = c >> 2, ch = c & 3;
            const __nv_bfloat16* gp = gsrc[sel] +
                (size_t)((sel < 2 ? bm : bn) + row) * K + k0 + ch * 8;
            __nv_bfloat16* sp = (sel < 2)
                ? &sA[buf][sel][row][ch * 8]
                : &sB[buf][sel - 2][row][ch * 8];
            cpa16(scvt(sp), gp);
        }
        asm volatile("cp.async.commit_group;");
    };

    float acc[2][4][4];
    #pragma unroll
    for (int mt = 0; mt < 2; mt++)
        #pragma unroll
        for (int nt = 0; nt < 4; nt++)
            #pragma unroll
            for (int u = 0; u < 4; u++) acc[mt][nt][u] = 0.f;

    issue(0);

    for (int s = 0; s < NS; s++) {
        if (s + 1 < NS) { issue(s + 1); asm volatile("cp.async.wait_group 1;"); }
        else            { asm volatile("cp.async.wait_group 0;"); }
        __syncthreads();
        const int buf = s & 1;

        #pragma unroll
        for (int kk = 0; kk < 2; kk++) {
            unsigned ah[2][4], al[2][4];
            #pragma unroll
            for (int mt = 0; mt < 2; mt++) {
                int row = wm * 32 + mt * 16 + (lane & 15);
                int col = kk * 16 + (lane >> 4) * 8;
                ldm4(ah[mt], scvt(&sA[buf][0][row][col]));
                ldm4(al[mt], scvt(&sA[buf][1][row][col]));
            }
            unsigned bh[4][2], bl[4][2];
            #pragma unroll
            for (int nt = 0; nt < 4; nt++) {
                int n = wn * 32 + nt * 8 + (lane >> 2);
                int w0 = kk * 16 + (lane & 3) * 2;
                bh[nt][0] = *(const unsigned*)&sB[buf][0][n][w0];
                bh[nt][1] = *(const unsigned*)&sB[buf][0][n][w0 + 8];
                bl[nt][0] = *(const unsigned*)&sB[buf][1][n][w0];
                bl[nt][1] = *(const unsigned*)&sB[buf][1][n][w0 + 8];
            }
            #pragma unroll
            for (int mt = 0; mt < 2; mt++)
                #pragma unroll
                for (int nt = 0; nt < 4; nt++) {
                    mma_bf16(acc[mt][nt], ah[mt], bl[nt]);
                    mma_bf16(acc[mt][nt], al[mt], bh[nt]);
                    mma_bf16(acc[mt][nt], ah[mt], bh[nt]);
                }
        }
        __syncthreads();
    }

    const int r4 = lane >> 2;
    const int kq = lane & 3;
    #pragma unroll
    for (int nt = 0; nt < 4; nt++) {
        int col = bn + wn * 32 + nt * 8 + 2 * kq;
        float2 bb = make_float2(0.f, 0.f);
        if (bias) bb = *(const float2*)(bias + col);
        #pragma unroll
        for (int mt = 0; mt < 2; mt++) {
            int row0 = bm + wm * 32 + mt * 16 + r4;
            float2 v0 = make_float2(acc[mt][nt][0] + bb.x, acc[mt][nt][1] + bb.y);
            float2 v1 = make_float2(acc[mt][nt][2] + bb.x, acc[mt][nt][3] + bb.y);
            if (C) {
                *(float2*)(C + (size_t)row0 * N + col) = v0;
                *(float2*)(C + (size_t)(row0 + 8) * N + col) = v1;
            }
            if (Chi) {
                __nv_bfloat16 h0 = __float2bfloat16_rn(v0.x);
                __nv_bfloat16 h1 = __float2bfloat16_rn(v0.y);
                __nv_bfloat16 h2 = __float2bfloat16_rn(v1.x);
                __nv_bfloat16 h3 = __float2bfloat16_rn(v1.y);
                *(__nv_bfloat162*)(Chi + (size_t)row0 * N + col) = __nv_bfloat162(h0, h1);
                *(__nv_bfloat162*)(Chi + (size_t)(row0 + 8) * N + col) = __nv_bfloat162(h2, h3);
                *(__nv_bfloat162*)(Clo + (size_t)row0 * N + col) = __nv_bfloat162(
                    __float2bfloat16_rn(v0.x - __bfloat162float(h0)),
                    __float2bfloat16_rn(v0.y - __bfloat162float(h1)));
                *(__nv_bfloat162*)(Clo + (size_t)(row0 + 8) * N + col) = __nv_bfloat162(
                    __float2bfloat16_rn(v1.x - __bfloat162float(h2)),
                    __float2bfloat16_rn(v1.y - __bfloat162float(h3)));
            }
        }
    }
}

// ---------------------------------------------------------------------------
// Key index mapping (verified rounds 1-16).
// ---------------------------------------------------------------------------
__device__ __forceinline__ int key_gpos(int p, int f, int i, int j)
{
    const int g = f >> 5;
    const int r = f & 31;
    int pos, sp;
    if (p == 0) {
        sp = (f < 64) ? 1 : 2;
        pos = (g == 0) ? r * 32 + i
            : (g == 1) ? 480 + r
            : (g == 2) ? r * 32 + 15
            :            j * 32 + r;
    } else if (p == 1) {
        sp = (f < 64) ? 0 : 2;
        pos = (g == 0) ? r * 32 + i
            : (g == 1) ? 480 + r
            : (g == 2) ? r * 32 + (31 - j)
            :            480 + r;
    } else {
        sp = (f < 64) ? 0 : 2;
        pos = (g == 0) ? r * 32 + 15
            : (g == 1) ? j * 32 + r
            : (g == 2) ? r * 32 + 15
            :            (31 - i) * 32 + r;
    }
    return sp * 1024 + pos;
}

__device__ __forceinline__ int k1_f(int p, int s)
{
    int g = s >> 5;
    if (g >= 3 - p) g++;
    return g * 32 + (s & 31);
}

// ---------------------------------------------------------------------------
// K2 (verified r15/r16): PDL sync before staging; trigger right after
// (so k13 launches knowing gemm1 is complete) and overlap k13's score phase.
// ---------------------------------------------------------------------------
__global__ __launch_bounds__(256) void k2_mid()
{
    const int j = blockIdx.x, h = blockIdx.y, p = blockIdx.z;
    const int tid = threadIdx.x;
    const int warp = tid >> 5, lane = tid & 31;
    const int wm = warp & 1, wn = warp >> 1;     // wn in 0..3
    const int qbase = p * 1024 + j * 32;

    __shared__ int spos[32];
    __shared__ __align__(16) __nv_bfloat16 Qh[32][72], Ql[32][72];
    __shared__ __align__(16) __nv_bfloat16 Kh[32][72], Kl[32][72];
    __shared__ float Sj[32][36];
    __shared__ __align__(16) __nv_bfloat16 Pjh[32][40], Pjl[32][40];

    if (tid < 32) spos[tid] = key_gpos(p, (3 - p) * 32 + tid, 0, j);
    __syncthreads();

    cudaGridDependencySynchronize();            // gemm1 (q split) complete
    cudaTriggerProgrammaticLaunchCompletion();  // let k13 start its score phase

    {
        int row = tid >> 3, ch = (tid & 7) * 8;
        size_t qo = (size_t)(qbase + row) * DDIM + h * 64 + ch;
        cpa16(scvt(&Qh[row][ch]), g_qhi + qo);
        cpa16(scvt(&Ql[row][ch]), g_qlo + qo);
        size_t ko = (size_t)spos[row] * DDIM + h * 64 + ch;
        cpa16(scvt(&Kh[row][ch]), g_qhi + ko);
        cpa16(scvt(&Kl[row][ch]), g_qlo + ko);
    }
    asm volatile("cp.async.commit_group;");
    asm volatile("cp.async.wait_group 0;");
    __syncthreads();

    const int r4 = lane >> 2, kq = lane & 3;

    // S_j(32q x 32f) = Q @ Kj^T : warp = (wm m-tile) x (wn 8 f-cols)
    {
        float sacc[4] = {0.f, 0.f, 0.f, 0.f};
        #pragma unroll
        for (int kk = 0; kk < 4; kk++) {
            unsigned ah[4], al[4];
            const int arow = wm * 16 + (lane & 15);
            const int acol = kk * 16 + (lane >> 4) * 8;
            ldm4(ah, scvt(&Qh[arow][acol]));
            ldm4(al, scvt(&Ql[arow][acol]));
            unsigned bh[2], bl[2];
            int n = wn * 8 + (lane >> 2);
            int c0 = kk * 16 + (lane & 3) * 2;
            bh[0] = *(const unsigned*)&Kh[n][c0];
            bh[1] = *(const unsigned*)&Kh[n][c0 + 8];
            bl[0] = *(const unsigned*)&Kl[n][c0];
            bl[1] = *(const unsigned*)&Kl[n][c0 + 8];
            mma_bf16(sacc, ah, bl);
            mma_bf16(sacc, al, bh);
            mma_bf16(sacc, ah, bh);
        }
        int q0 = wm * 16 + r4;
        int f = wn * 8 + 2 * kq;
        Sj[q0][f]       = sacc[0] * 0.125f;
        Sj[q0][f + 1]   = sacc[1] * 0.125f;
        Sj[q0 + 8][f]     = sacc[2] * 0.125f;
        Sj[q0 + 8][f + 1] = sacc[3] * 0.125f;
    }
    __syncthreads();

    // local softmax + Pj split on threads 0..127
    if (tid < 128) {
        const int qs = tid >> 2, l4 = tid & 3;
        float vals[8];
        float mj = -1e30f;
        #pragma unroll
        for (int u = 0; u < 8; u++) {
            vals[u] = Sj[qs][l4 + 4 * u];
            mj = fmaxf(mj, vals[u]);
        }
        mj = fmaxf(mj, __shfl_xor_sync(0xffffffffu, mj, 2));
        mj = fmaxf(mj, __shfl_xor_sync(0xffffffffu, mj, 1));
        float sumj = 0.f;
        #pragma unroll
        for (int u = 0; u < 8; u++) { vals[u] = __expf(vals[u] - mj); sumj += vals[u]; }
        sumj += __shfl_xor_sync(0xffffffffu, sumj, 2);
        sumj += __shfl_xor_sync(0xffffffffu, sumj, 1);
        if (l4 == 0)
            g_MS[(unsigned)(qbase + qs) * 8 + h] = make_float2(mj, sumj);
        #pragma unroll
        for (int u = 0; u < 8; u++)
            Sj[qs][l4 + 4 * u] = vals[u];
        __syncwarp();
        split8(&Sj[qs][l4 * 8], &Pjh[qs][l4 * 8], &Pjl[qs][l4 * 8]);
    }
    __syncthreads();

    // O_j'(32q x 64d) = P_j'(32x32) @ K_j(32x64): warp = wm x (wn 16 d-cols)
    {
        float oacc[2][4];
        #pragma unroll
        for (int nt = 0; nt < 2; nt++)
            #pragma unroll
            for (int u = 0; u < 4; u++) oacc[nt][u] = 0.f;

        #pragma unroll
        for (int ks = 0; ks < 2; ks++) {
            const int k0 = ks * 16;
            unsigned ah[4], al[4];
            const int arow = wm * 16 + (lane & 15);
            const int acol = k0 + (lane >> 4) * 8;
            ldm4(ah, scvt(&Pjh[arow][acol]));
            ldm4(al, scvt(&Pjl[arow][acol]));
            unsigned bh[2][2], bl[2][2];
            const int brow = k0 + (lane & 7) + 8 * ((lane >> 3) & 1);
            #pragma unroll
            for (int nt = 0; nt < 2; nt++) {
                int bcol = wn * 16 + nt * 8;
                ldm2t(bh[nt], scvt(&Kh[brow][bcol]));
                ldm2t(bl[nt], scvt(&Kl[brow][bcol]));
            }
            #pragma unroll
            for (int nt = 0; nt < 2; nt++) {
                mma_bf16(oacc[nt], ah, bl[nt]);
                mma_bf16(oacc[nt], al, bh[nt]);
                mma_bf16(oacc[nt], ah, bh[nt]);
            }
        }
        #pragma unroll
        for (int nt = 0; nt < 2; nt++) {
            int d = wn * 16 + nt * 8 + 2 * kq;
            #pragma unroll
            for (int half = 0; half < 2; half++) {
                int q0 = wm * 16 + r4 + half * 8;
                *(float2*)(g_ao + (size_t)(qbase + q0) * DDIM + h * 64 + d) =
                    make_float2(oacc[nt][half*2], oacc[nt][half*2+1]);
            }
        }
    }
}

// ---------------------------------------------------------------------------
// K13 (verified r16 body). PDL: staging + score phase need only gemm1 data
// (guaranteed complete before k2's trigger); grid-dependency sync moved to
// just before the combine phase, which reads k2's (mj,sumj) / O_j'.
// ---------------------------------------------------------------------------
struct K13Smem {
    int spos[96];
    float2 pstat[4][32];    // [wn][row] partial (m, s)
    float2 minv[32];        // per row: (m, 1/total)
    float  coef[32];        // per row: e^(mj-m)/total
    union {
        struct {
            __align__(16) __nv_bfloat16 Qh[32][72];
            __align__(16) __nv_bfloat16 Ql[32][72];
        } q;
        struct {
            __align__(16) __nv_bfloat16 Ph[32][104];
            __align__(16) __nv_bfloat16 Pl[32][104];
        } pp;
    } u;
    __align__(16) __nv_bfloat16 Kh[96][72];
    __align__(16) __nv_bfloat16 Kl[96][72];
};

__global__ __launch_bounds__(256) void k13_fused()
{
    const int i = blockIdx.x, h = blockIdx.y, p = blockIdx.z;
    const int tid = threadIdx.x;
    const int warp = tid >> 5, lane = tid & 31;
    const int wm = warp & 1, wn = warp >> 1;   // wn in 0..3

    extern __shared__ char raw13[];
    K13Smem* sm = (K13Smem*)raw13;

    if (tid < 96) sm->spos[tid] = key_gpos(p, k1_f(p, tid), i, 0);
    __syncthreads();

    // group A: Q + K rows 0..47  (reads only gemm1's q split — safe pre-sync)
    {
        int row = tid >> 3, ch = (tid & 7) * 8;
        size_t off = (size_t)(p * 1024 + row * 32 + i) * DDIM + h * 64 + ch;
        cpa16(scvt(&sm->u.q.Qh[row][ch]), g_qhi + off);
        cpa16(scvt(&sm->u.q.Ql[row][ch]), g_qlo + off);
    }
    #pragma unroll
    for (int it = 0; it < 2; it++) {
        int idx = tid + 256 * it;
        if (idx < 384) {
            int row = idx >> 3, ch = (idx & 7) * 8;
            size_t off = (size_t)sm->spos[row] * DDIM + h * 64 + ch;
            cpa16(scvt(&sm->Kh[row][ch]), g_qhi + off);
            cpa16(scvt(&sm->Kl[row][ch]), g_qlo + off);
        }
    }
    asm volatile("cp.async.commit_group;");
    // group B: K rows 48..95
    #pragma unroll
    for (int it = 0; it < 2; it++) {
        int idx = tid + 256 * it;
        if (idx < 384) {
            int row = 48 + (idx >> 3), ch = (idx & 7) * 8;
            size_t off = (size_t)sm->spos[row] * DDIM + h * 64 + ch;
            cpa16(scvt(&sm->Kh[row][ch]), g_qhi + off);
            cpa16(scvt(&sm->Kl[row][ch]), g_qlo + off);
        }
    }
    asm volatile("cp.async.commit_group;");

    asm volatile("cp.async.wait_group 1;");
    __syncthreads();                                // Q + K[0..48) visible

    const int r4 = lane >> 2, kq = lane & 3;

    float acc[3][4];
    #pragma unroll
    for (int nt = 0; nt < 3; nt++)
        #pragma unroll
        for (int u = 0; u < 4; u++) acc[nt][u] = 0.f;

    auto score_phase = [&]() {
        #pragma unroll
        for (int kk = 0; kk < 4; kk++) {
            unsigned ah[4], al[4];
            const int arow = wm * 16 + (lane & 15);
            const int acol = kk * 16 + (lane >> 4) * 8;
            ldm4(ah, scvt(&sm->u.q.Qh[arow][acol]));
            ldm4(al, scvt(&sm->u.q.Ql[arow][acol]));
            unsigned bh[3][2], bl[3][2];
            #pragma unroll
            for (int nt = 0; nt < 3; nt++) {
                int n = wn * 24 + nt * 8 + (lane >> 2);
                int c0 = kk * 16 + (lane & 3) * 2;
                bh[nt][0] = *(const unsigned*)&sm->Kh[n][c0];
                bh[nt][1] = *(const unsigned*)&sm->Kh[n][c0 + 8];
                bl[nt][0] = *(const unsigned*)&sm->Kl[n][c0];
                bl[nt][1] = *(const unsigned*)&sm->Kl[n][c0 + 8];
            }
            #pragma unroll
            for (int nt = 0; nt < 3; nt++) {
                mma_bf16(acc[nt], ah, bl[nt]);
                mma_bf16(acc[nt], al, bh[nt]);
                mma_bf16(acc[nt], ah, bh[nt]);
            }
        }
        #pragma unroll
        for (int nt = 0; nt < 3; nt++)
            #pragma unroll
            for (int u = 0; u < 4; u++) acc[nt][u] *= 0.125f;

        #pragma unroll
        for (int half = 0; half < 2; half++) {
            float m = -1e30f;
            #pragma unroll
            for (int nt = 0; nt < 3; nt++) {
                m = fmaxf(m, acc[nt][half*2]);
                m = fmaxf(m, acc[nt][half*2+1]);
            }
            m = fmaxf(m, __shfl_xor_sync(0xffffffffu, m, 1));
            m = fmaxf(m, __shfl_xor_sync(0xffffffffu, m, 2));
            float s = 0.f;
            #pragma unroll
            for (int nt = 0; nt < 3; nt++) {
                s += __expf(acc[nt][half*2]   - m);
                s += __expf(acc[nt][half*2+1] - m);
            }
            s += __shfl_xor_sync(0xffffffffu, s, 1);
            s += __shfl_xor_sync(0xffffffffu, s, 2);
            if (kq == 0)
                sm->pstat[wn][wm*16 + half*8 + r4] = make_float2(m, s);
        }
    };

    if (wn < 2) score_phase();          // slots 0..47 only
    asm volatile("cp.async.wait_group 0;");
    __syncthreads();                     // K[48..96) visible
    if (wn >= 2) score_phase();          // slots 48..95
    __syncthreads();

    // ---- wait for k2's (mj,sumj) / O_j' before consuming them ----
    cudaGridDependencySynchronize();

    // ---- combine with (mj, sumj): one thread per row ----
    if (tid < 32) {
        int row = tid;
        float m = sm->pstat[0][row].x;
        m = fmaxf(m, sm->pstat[1][row].x);
        m = fmaxf(m, sm->pstat[2][row].x);
        m = fmaxf(m, sm->pstat[3][row].x);
        float2 msj = g_MS[(unsigned)(p*1024 + row*32 + i) * 8 + h];
        m = fmaxf(m, msj.x);
        float tot = msj.y * __expf(msj.x - m);
        #pragma unroll
        for (int w = 0; w < 4; w++)
            tot += sm->pstat[w][row].y * __expf(sm->pstat[w][row].x - m);
        float inv = 1.0f / tot;
        sm->minv[row] = make_float2(m, inv);
        sm->coef[row] = __expf(msj.x - m) * inv;
    }
    __syncthreads();

    // ---- normalize in registers, write bf16 P split to smem (over Q) ----
    {
        const int q0 = wm * 16 + r4;
        const int q1 = q0 + 8;
        float2 mi0 = sm->minv[q0];
        float2 mi1 = sm->minv[q1];
        #pragma unroll
        for (int nt = 0; nt < 3; nt++) {
            int slot = wn * 24 + nt * 8 + 2 * kq;
            float p0 = __expf(acc[nt][0] - mi0.x) * mi0.y;
            float p1 = __expf(acc[nt][1] - mi0.x) * mi0.y;
            float p2 = __expf(acc[nt][2] - mi1.x) * mi1.y;
            float p3 = __expf(acc[nt][3] - mi1.x) * mi1.y;
            __nv_bfloat16 h0 = __float2bfloat16_rn(p0);
            __nv_bfloat16 h1 = __float2bfloat16_rn(p1);
            __nv_bfloat16 h2 = __float2bfloat16_rn(p2);
            __nv_bfloat16 h3 = __float2bfloat16_rn(p3);
            *(__nv_bfloat162*)&sm->u.pp.Ph[q0][slot] = __nv_bfloat162(h0, h1);
            *(__nv_bfloat162*)&sm->u.pp.Ph[q1][slot] = __nv_bfloat162(h2, h3);
            *(__nv_bfloat162*)&sm->u.pp.Pl[q0][slot] = __nv_bfloat162(
                __float2bfloat16_rn(p0 - __bfloat162float(h0)),
                __float2bfloat16_rn(p1 - __bfloat162float(h1)));
            *(__nv_bfloat162*)&sm->u.pp.Pl[q1][slot] = __nv_bfloat162(
                __float2bfloat16_rn(p2 - __bfloat162float(h2)),
                __float2bfloat16_rn(p3 - __bfloat162float(h3)));
        }
    }
    __syncthreads();

    // ---- hoist epilogue inputs (coef + old O_j') above the output MMA ----
    float  cf[2];
    float2 oldv[2][2];
    size_t offs[2][2];
    #pragma unroll
    for (int half = 0; half < 2; half++) {
        int q0 = wm * 16 + r4 + half * 8;
        cf[half] = sm->coef[q0];
        #pragma unroll
        for (int nt = 0; nt < 2; nt++) {
            int d = wn * 16 + nt * 8 + 2 * kq;
            offs[nt][half] = (size_t)(p*1024 + q0*32 + i) * DDIM + h*64 + d;
            oldv[nt][half] = *(const float2*)(g_ao + offs[nt][half]);
        }
    }

    // ---- output MMA: warp = m-tile wm x 16 d-cols (wn*16..wn*16+15) ----
    float oacc[2][4];
    #pragma unroll
    for (int nt = 0; nt < 2; nt++)
        #pragma unroll
        for (int u = 0; u < 4; u++) oacc[nt][u] = 0.f;

    #pragma unroll
    for (int ks = 0; ks < 6; ks++) {
        const int k0 = ks * 16;
        unsigned ah[4], al[4];
        const int arow = wm * 16 + (lane & 15);
        const int acol = k0 + (lane >> 4) * 8;
        ldm4(ah, scvt(&sm->u.pp.Ph[arow][acol]));
        ldm4(al, scvt(&sm->u.pp.Pl[arow][acol]));
        unsigned bh[2][2], bl[2][2];
        const int brow = k0 + (lane & 7) + 8 * ((lane >> 3) & 1);
        #pragma unroll
        for (int nt = 0; nt < 2; nt++) {
            int bcol = wn * 16 + nt * 8;
            ldm2t(bh[nt], scvt(&sm->Kh[brow][bcol]));
            ldm2t(bl[nt], scvt(&sm->Kl[brow][bcol]));
        }
        #pragma unroll
        for (int nt = 0; nt < 2; nt++) {
            mma_bf16(oacc[nt], ah, bl[nt]);
            mma_bf16(oacc[nt], al, bh[nt]);
            mma_bf16(oacc[nt], ah, bh[nt]);
        }
    }

    // ---- epilogue: O = O96 + coef * O_j'; write ao bf16 split ----
    #pragma unroll
    for (int nt = 0; nt < 2; nt++) {
        #pragma unroll
        for (int half = 0; half < 2; half++) {
            float c = cf[half];
            float v0 = oacc[nt][half * 2]     + c * oldv[nt][half].x;
            float v1 = oacc[nt][half * 2 + 1] + c * oldv[nt][half].y;
            __nv_bfloat16 h0 = __float2bfloat16_rn(v0);
            __nv_bfloat16 h1 = __float2bfloat16_rn(v1);
            *(__nv_bfloat162*)(g_Ahi + offs[nt][half]) = __nv_bfloat162(h0, h1);
            *(__nv_bfloat162*)(g_Alo + offs[nt][half]) = __nv_bfloat162(
                __float2bfloat16_rn(v0 - __bfloat162float(h0)),
                __float2bfloat16_rn(v1 - __bfloat162float(h1)));
        }
    }
}

// ---------------------------------------------------------------------------
extern "C" void kernel_launch(void* const* d_in, const int* in_sizes, int n_in,
                              void* d_out, int out_size)
{
    const float* x  = (const float*)d_in[0];
    const float* Wq = (const float*)d_in[1];
    const float* Wo = (const float*)d_in[2];
    const float* bo = (const float*)d_in[3];
    float* out = (float*)d_out;

    __nv_bfloat16 *ahi, *alo, *bhi, *blo, *b2hi, *b2lo, *qhi, *qlo;
    cudaGetSymbolAddress((void**)&ahi,  g_Ahi);
    cudaGetSymbolAddress((void**)&alo,  g_Alo);
    cudaGetSymbolAddress((void**)&bhi,  g_Bhi);
    cudaGetSymbolAddress((void**)&blo,  g_Blo);
    cudaGetSymbolAddress((void**)&b2hi, g_B2hi);
    cudaGetSymbolAddress((void**)&b2lo, g_B2lo);
    cudaGetSymbolAddress((void**)&qhi,  g_qhi);
    cudaGetSymbolAddress((void**)&qlo,  g_qlo);

    cudaFuncSetAttribute(k13_fused, cudaFuncAttributeMaxDynamicSharedMemorySize,
                         (int)sizeof(K13Smem));

    const dim3 gridG(512 / 64, ROWS / 64);  // (8, 48)
    const dim3 gridA(32, 8, 3);

    cudaLaunchAttribute pdl[1];
    pdl[0].id = cudaLaunchAttributeProgrammaticStreamSerialization;
    pdl[0].val.programmaticStreamSerializationAllowed = 1;

    // 1) splits (plain launch — head of chain)
    split_all<<<(NX4 + 2 * NW4) / 256, 256>>>(x, Wq, Wo);

    // 2) gemm1 (PDL successor of split)
    {
        cudaLaunchConfig_t cfg{};
        cfg.gridDim = gridG; cfg.blockDim = dim3(128);
        cfg.stream = 0; cfg.attrs = pdl; cfg.numAttrs = 1;
        cudaLaunchKernelEx(&cfg, gemm_bf16,
            (const __nv_bfloat16*)ahi, (const __nv_bfloat16*)alo,
            (const __nv_bfloat16*)bhi, (const __nv_bfloat16*)blo,
            (const float*)nullptr, (float*)nullptr,
            (__nv_bfloat16*)qhi, (__nv_bfloat16*)qlo, ROWS, 512, 512);
    }
    // 3) k2 (PDL successor of gemm1)
    {
        cudaLaunchConfig_t cfg{};
        cfg.gridDim = gridA; cfg.blockDim = dim3(256);
        cfg.stream = 0; cfg.attrs = pdl; cfg.numAttrs = 1;
        cudaLaunchKernelEx(&cfg, k2_mid);
    }
    // 4) k13 (PDL successor of k2 — launches at k2's trigger; overlaps score)
    {
        cudaLaunchConfig_t cfg{};
        cfg.gridDim = gridA; cfg.blockDim = dim3(256);
        cfg.dynamicSmemBytes = sizeof(K13Smem);
        cfg.stream = 0; cfg.attrs = pdl; cfg.numAttrs = 1;
        cudaLaunchKernelEx(&cfg, k13_fused);
    }
    // 5) gemm2 (PDL successor of k13)
    {
        cudaLaunchConfig_t cfg{};
        cfg.gridDim = gridG; cfg.blockDim = dim3(128);
        cfg.stream = 0; cfg.attrs = pdl; cfg.numAttrs = 1;
        cudaLaunchKernelEx(&cfg, gemm_bf16,
            (const __nv_bfloat16*)ahi, (const __nv_bfloat16*)alo,
            (const __nv_bfloat16*)b2hi, (const __nv_bfloat16*)b2lo,
            bo, out, (__nv_bfloat16*)nullptr, (__nv_bfloat16*)nullptr,
            ROWS, 512, 512);
    }
}